// round 11
// baseline (speedup 1.0000x reference)
#include <cuda_runtime.h>
#include <math.h>

#define BS   2
#define NP   4096
#define CH   64
#define IMH  128
#define IMW  256
#define QPB  (IMH*IMW)
#define TPB  256
#define PXB  128
#define BSZ  8
#define NBX  (IMW/BSZ)
#define NBY  (IMH/BSZ)
#define NBINS (NBX*NBY)
#define CAND_MAX 512
#define CPAD (CAND_MAX + 8)

typedef unsigned long long ull;

__device__ float  g_featT[BS * NP * CH];
__device__ float  g_woutT[CH * CH];
__device__ float4 g_binned[BS * NP];
__device__ int    g_prefix[BS * (NBINS + 1)];

__device__ __forceinline__ ull pk2(float lo, float hi) {
    ull r; asm("mov.b64 %0,{%1,%2};" : "=l"(r) : "f"(lo), "f"(hi)); return r;
}
__device__ __forceinline__ void upk2(float& lo, float& hi, ull v) {
    asm("mov.b64 {%0,%1},%2;" : "=f"(lo), "=f"(hi) : "l"(v));
}
__device__ __forceinline__ ull fma2_(ull a, ull b, ull c) {
    ull d; asm("fma.rn.f32x2 %0,%1,%2,%3;" : "=l"(d) : "l"(a), "l"(b), "l"(c)); return d;
}
__device__ __forceinline__ ull mul2_(ull a, ull b) {
    ull d; asm("mul.rn.f32x2 %0,%1,%2;" : "=l"(d) : "l"(a), "l"(b)); return d;
}
__device__ __forceinline__ ull add2_(ull a, ull b) {
    ull d; asm("add.rn.f32x2 %0,%1,%2;" : "=l"(d) : "l"(a), "l"(b)); return d;
}
__device__ __forceinline__ ull sub2_(ull a, ull b) {
    ull d; asm("sub.rn.f32x2 %0,%1,%2;" : "=l"(d) : "l"(a), "l"(b)); return d;
}
__device__ __forceinline__ float tanh_ap(float x) {
    float y; asm("tanh.approx.f32 %0,%1;" : "=f"(y) : "f"(x)); return y;
}

__global__ __launch_bounds__(512, 1)
void k_prep(const float* __restrict__ uv, const float* __restrict__ feat,
            const float* __restrict__ w_out) {
    __shared__ int s_cnt[NBINS];
    __shared__ int s_pfx[NBINS];
    __shared__ float s_tile[64][65];
    const int t = threadIdx.x;
    const int bid = blockIdx.x;

    if (bid < BS) {
        const int b = bid;
        s_cnt[t] = 0;
        __syncthreads();
        const float* uvb = uv + b * 2 * NP;
        float4 myp[8]; int mybin[8];
        #pragma unroll
        for (int r = 0; r < 8; ++r) {
            int i = t + r * 512;
            float px = uvb[i], py = uvb[NP + i];
            float psq = __fadd_rn(__fmul_rn(px, px), __fmul_rn(py, py));
            int bx = min(max((int)(px * (1.0f / BSZ)), 0), NBX - 1);
            int by = min(max((int)(py * (1.0f / BSZ)), 0), NBY - 1);
            mybin[r] = by * NBX + bx;
            myp[r] = make_float4(px, py, psq, __int_as_float(i));
            atomicAdd(&s_cnt[mybin[r]], 1);
        }
        __syncthreads();
        int v = s_cnt[t];
        s_pfx[t] = v;
        __syncthreads();
        for (int d = 1; d < NBINS; d <<= 1) {
            int add = (t >= d) ? s_pfx[t - d] : 0;
            __syncthreads();
            s_pfx[t] += add;
            __syncthreads();
        }
        g_prefix[b * (NBINS + 1) + t + 1] = s_pfx[t];
        if (t == 0) g_prefix[b * (NBINS + 1)] = 0;
        s_cnt[t] = s_pfx[t] - v;
        __syncthreads();
        #pragma unroll
        for (int r = 0; r < 8; ++r) {
            int pos = atomicAdd(&s_cnt[mybin[r]], 1);
            g_binned[b * NP + pos] = myp[r];
        }
    } else if (bid < BS + BS * 64) {
        int tb = bid - BS;
        int b  = tb >> 6;
        int i0 = (tb & 63) * 64;
        int c  = t >> 3, j = t & 7;
        #pragma unroll
        for (int rep = 0; rep < 2; ++rep) {
            int i4 = j + rep * 8;
            float4 v = *(const float4*)(feat + ((size_t)(b * CH + c) * NP + i0 + i4 * 4));
            s_tile[i4 * 4 + 0][c] = v.x;
            s_tile[i4 * 4 + 1][c] = v.y;
            s_tile[i4 * 4 + 2][c] = v.z;
            s_tile[i4 * 4 + 3][c] = v.w;
        }
        __syncthreads();
        int i = t >> 3;
        #pragma unroll
        for (int rep = 0; rep < 2; ++rep) {
            int c4 = j + rep * 8;
            float4 w;
            w.x = s_tile[i][c4 * 4 + 0];
            w.y = s_tile[i][c4 * 4 + 1];
            w.z = s_tile[i][c4 * 4 + 2];
            w.w = s_tile[i][c4 * 4 + 3];
            *(float4*)(g_featT + ((size_t)(b * NP + i0 + i) << 6) + c4 * 4) = w;
        }
    } else {
        int c = t >> 3, j = t & 7;
        #pragma unroll
        for (int rep = 0; rep < 2; ++rep) {
            int i4 = j + rep * 8;
            float4 v = *(const float4*)(w_out + (size_t)c * CH + i4 * 4);
            s_tile[i4 * 4 + 0][c] = v.x;
            s_tile[i4 * 4 + 1][c] = v.y;
            s_tile[i4 * 4 + 2][c] = v.z;
            s_tile[i4 * 4 + 3][c] = v.w;
        }
        __syncthreads();
        int i = t >> 3;
        #pragma unroll
        for (int rep = 0; rep < 2; ++rep) {
            int c4 = j + rep * 8;
            float4 w;
            w.x = s_tile[i][c4 * 4 + 0];
            w.y = s_tile[i][c4 * 4 + 1];
            w.z = s_tile[i][c4 * 4 + 2];
            w.w = s_tile[i][c4 * 4 + 3];
            *(float4*)(g_woutT + (size_t)i * CH + c4 * 4) = w;
        }
    }
}

#define INSERT(dd, pi, sl) {                                                   \
    if ((dd) < d2b || ((dd) == d2b && (pi) < i2)) {                            \
        if ((dd) < d1 || ((dd) == d1 && (pi) < i1)) {                          \
            d2b = d1; i2 = i1; s2 = s1;                                        \
            if ((dd) < d0 || ((dd) == d0 && (pi) < i0))                        \
                 { d1 = d0; i1 = i0; s1 = s0; d0 = (dd); i0 = (pi); s0 = (sl); } \
            else { d1 = (dd); i1 = (pi); s1 = (sl); }                          \
        } else { d2b = (dd); i2 = (pi); s2 = (sl); }                           \
    } }

// SMEM: woutT[4096] | consts | HP (9 h-rows + 3 idx-rows = 12*128) | union{cand+mrg | fin}
#define SM_WOUT  0
#define SM_W2A   (SM_WOUT + CH*CH)
#define SM_W2B   (SM_W2A + CH)
#define SM_W2C   (SM_W2B + CH)
#define SM_B2    (SM_W2C + CH)
#define SM_BOUT  (SM_B2 + CH)
#define SM_W1    (SM_BOUT + CH)
#define SM_B1    (SM_W1 + 16)
#define SM_HP    (SM_B1 + 8)
#define SM_UNION (SM_HP + 12*PXB)
#define SM_PX    SM_UNION
#define SM_PY    (SM_PX + CPAD)
#define SM_PSQ   (SM_PY + CPAD)
#define SM_IDX   (SM_PSQ + CPAD)
#define SM_MRG   (SM_IDX + CPAD)
#define SM_FIN   SM_UNION
#define UNION_FLOATS ((CH*PXB) > (4*CPAD + 9*PXB) ? (CH*PXB) : (4*CPAD + 9*PXB))
#define SMEM_FLOATS (SM_UNION + UNION_FLOATS)
#define SMEM_BYTES  (SMEM_FLOATS * 4)

__global__ __launch_bounds__(TPB, 4)
void k_main(const float* __restrict__ w1, const float* __restrict__ b1,
            const float* __restrict__ w2, const float* __restrict__ b2,
            const float* __restrict__ b_out,
            float* __restrict__ out)
{
    extern __shared__ float sm[];
    float* woutT_s = sm + SM_WOUT;
    float* candPx  = sm + SM_PX;
    float* candPy  = sm + SM_PY;
    float* candPsq = sm + SM_PSQ;
    int*   candIdx = (int*)(sm + SM_IDX);
    float* mrgD    = sm + SM_MRG;
    int*   mrgI    = (int*)(sm + SM_MRG + 3*PXB);
    int*   mrgS    = (int*)(sm + SM_MRG + 6*PXB);
    float* hS      = sm + SM_HP;                 // rows 0..8: h[3k+j]; rows 9..11: nidx
    int*   nidxS   = (int*)(sm + SM_HP + 9*PXB);
    float* fin_s   = sm + SM_FIN;
    float* w2aF = sm + SM_W2A; float* w2bF = sm + SM_W2B; float* w2cF = sm + SM_W2C;
    float* b2F  = sm + SM_B2;  float* boutF = sm + SM_BOUT;
    float* w1s = sm + SM_W1;   float* b1s = sm + SM_B1;
    __shared__ int s_startA[3], s_cntA[3], s_offA[3], s_totalA;

    const int tid  = threadIdx.x;
    const int b    = blockIdx.z;
    const int px   = tid & (PXB - 1);
    const int half = tid >> 7;
    const int tx   = px & 15, ty = px >> 4;
    const int gxi  = blockIdx.x * 16 + tx;
    const int gyi  = blockIdx.y * 8 + ty;
    const float gx = (float)gxi, gy = (float)gyi;
    const float qsq = gx * gx + gy * gy;

    const int tbx0 = blockIdx.x * 2;
    const int tby0 = blockIdx.y;
    const int bxlo = max(tbx0 - 1, 0), bxhi = min(tbx0 + 2, NBX - 1);
    const int bylo = max(tby0 - 1, 0), byhi = min(tby0 + 1, NBY - 1);
    const int nrows = byhi - bylo + 1;

    if (tid < nrows) {
        int row = bylo + tid;
        int s = g_prefix[b * (NBINS + 1) + row * NBX + bxlo];
        int e = g_prefix[b * (NBINS + 1) + row * NBX + bxhi + 1];
        s_startA[tid] = s; s_cntA[tid] = e - s;
    }
    {
        const float4* w4 = (const float4*)g_woutT;
        float4* wo4 = (float4*)woutT_s;
        #pragma unroll
        for (int r = 0; r < 4; ++r) wo4[tid + r * TPB] = w4[tid + r * TPB];
    }
    if (tid < CH) {
        w2aF[tid] = w2[tid * 3 + 0];
        w2bF[tid] = w2[tid * 3 + 1];
        w2cF[tid] = w2[tid * 3 + 2];
        b2F[tid]  = b2[tid];
        boutF[tid] = b_out[tid];
    }
    if (tid < 9) w1s[tid] = w1[tid];
    if (tid < 3) b1s[tid] = b1[tid];
    __syncthreads();
    if (tid == 0) {
        int off = 0;
        for (int r = 0; r < nrows; ++r) { s_offA[r] = off; off += s_cntA[r]; }
        s_totalA = off;
    }
    __syncthreads();
    const int total = s_totalA;
    const bool ovf = total > CAND_MAX;
    if (!ovf) {
        for (int r = 0; r < nrows; ++r) {
            int c = s_cntA[r], st = s_startA[r], of = s_offA[r];
            for (int i = tid; i < c; i += TPB) {
                float4 p = g_binned[b * NP + st + i];
                candPx[of + i] = p.x; candPy[of + i] = p.y;
                candPsq[of + i] = p.z; candIdx[of + i] = __float_as_int(p.w);
            }
        }
        if (tid < 8) {
            candPx[total + tid] = 0.f; candPy[total + tid] = 0.f;
            candPsq[total + tid] = 1e30f; candIdx[total + tid] = 0x7ffffff0;
        }
    }
    __syncthreads();

    // ---- Phase 1: split scan ----
    float d0 = INFINITY, d1 = INFINITY, d2b = INFINITY;
    int   i0 = 0x7fffffff, i1 = 0x7fffffff, i2 = 0x7fffffff;
    int   s0 = 0, s1 = 0, s2 = 0;
    bool  fb = false;
    const int nq  = (total + 3) >> 2;
    const int nqA = nq >> 1;
    if (!ovf) {
        const float4* px4  = (const float4*)candPx;
        const float4* py4  = (const float4*)candPy;
        const float4* psq4 = (const float4*)candPsq;
        const ull gx2 = pk2(gx, gx), gy2 = pk2(gy, gy), qsq2 = pk2(qsq, qsq);
        const int jlo = half ? nqA : 0;
        const int jhi = half ? nq : nqA;
        #pragma unroll 2
        for (int jq = jlo; jq < jhi; ++jq) {
            float4 PX = px4[jq], PY = py4[jq], PSQ = psq4[jq];
            ull crA = fma2_(pk2(PY.x, PY.y), gy2, mul2_(pk2(PX.x, PX.y), gx2));
            ull ddA = sub2_(add2_(qsq2, pk2(PSQ.x, PSQ.y)), add2_(crA, crA));
            ull crB = fma2_(pk2(PY.z, PY.w), gy2, mul2_(pk2(PX.z, PX.w), gx2));
            ull ddB = sub2_(add2_(qsq2, pk2(PSQ.z, PSQ.w)), add2_(crB, crB));
            float a0, a1, a2, a3;
            upk2(a0, a1, ddA); upk2(a2, a3, ddB);
            int base = 4 * jq;
            if (a0 <= d2b) { int pi = candIdx[base + 0]; INSERT(a0, pi, base + 0); }
            if (a1 <= d2b) { int pi = candIdx[base + 1]; INSERT(a1, pi, base + 1); }
            if (a2 <= d2b) { int pi = candIdx[base + 2]; INSERT(a2, pi, base + 2); }
            if (a3 <= d2b) { int pi = candIdx[base + 3]; INSERT(a3, pi, base + 3); }
        }
    }
    if (half) {
        mrgD[px] = d0; mrgD[PXB + px] = d1; mrgD[2 * PXB + px] = d2b;
        mrgI[px] = i0; mrgI[PXB + px] = i1; mrgI[2 * PXB + px] = i2;
        mrgS[px] = s0; mrgS[PXB + px] = s1; mrgS[2 * PXB + px] = s2;
    }
    __syncthreads();

    if (!half) {
        {   // merge B's triple
            float bd0 = mrgD[px], bd1 = mrgD[PXB + px], bd2 = mrgD[2 * PXB + px];
            int   bi0 = mrgI[px], bi1 = mrgI[PXB + px], bi2 = mrgI[2 * PXB + px];
            int   bs0 = mrgS[px], bs1 = mrgS[PXB + px], bs2 = mrgS[2 * PXB + px];
            INSERT(bd0, bi0, bs0);
            INSERT(bd1, bi1, bs1);
            INSERT(bd2, bi2, bs2);
        }
        float dl = (bxlo > 0)       ? (gx - (float)(bxlo * BSZ))       : 1e9f;
        float dr = (bxhi < NBX - 1) ? ((float)((bxhi + 1) * BSZ) - gx) : 1e9f;
        float dt = (bylo > 0)       ? (gy - (float)(bylo * BSZ))       : 1e9f;
        float db = (byhi < NBY - 1) ? ((float)((byhi + 1) * BSZ) - gy) : 1e9f;
        float dmin = fminf(fminf(dl, dr), fminf(dt, db));
        if (ovf || !(d2b + 0.25f <= dmin * dmin)) {
            fb = true;
            d0 = d1 = d2b = INFINITY; i0 = i1 = i2 = 0x7fffffff;
            const float4* gp = g_binned + b * NP;
            #pragma unroll 4
            for (int j = 0; j < NP; ++j) {
                float4 p = gp[j];
                float cr = __fmaf_rn(p.y, gy, __fmul_rn(p.x, gx));
                float dd = __fsub_rn(__fadd_rn(qsq, p.z), __fadd_rn(cr, cr));
                if (dd <= d2b) { int pi = __float_as_int(p.w); INSERT(dd, pi, j); }
            }
        }
        int nidx[3] = { i0, i1, i2 };
        int nsl[3]  = { s0, s1, s2 };
        #pragma unroll
        for (int k = 0; k < 3; ++k) {
            float pxx, pyy;
            if (!fb) { pxx = candPx[nsl[k]]; pyy = candPy[nsl[k]]; }
            else     { float4 p = g_binned[b * NP + nsl[k]]; pxx = p.x; pyy = p.y; }
            float dx = __fsub_rn(pxx, gx);
            float dy = __fsub_rn(pyy, gy);
            float nrm = __fsqrt_rn(__fadd_rn(__fmul_rn(dx, dx), __fmul_rn(dy, dy)));
            #pragma unroll
            for (int j = 0; j < 3; ++j) {
                float t = __fmaf_rn(w1s[j*3+2], nrm,
                          __fmaf_rn(w1s[j*3+1], dy, __fmul_rn(w1s[j*3+0], dx)));
                t = t + b1s[j];
                hS[(3 * k + j) * PXB + px] = (t >= 0.f) ? t : 0.1f * t;
            }
            nidxS[k * PXB + px] = nidx[k];
        }
    }
    __syncthreads();   // cand/mrg dead, HP live; fin_s may overwrite union

    // ---- Phase 2: channels split across halves ----
    {
        const ull HALF2 = 0x3F0000003F000000ULL;
        const ull* w2a2 = (const ull*)w2aF;
        const ull* w2b2 = (const ull*)w2bF;
        const ull* w2c2 = (const ull*)w2cF;
        const ull* b2p2 = (const ull*)b2F;
        ull hp0[3], hp1[3], hp2[3];
        #pragma unroll
        for (int k = 0; k < 3; ++k) {
            float h0v = hS[(3 * k + 0) * PXB + px];
            float h1v = hS[(3 * k + 1) * PXB + px];
            float h2v = hS[(3 * k + 2) * PXB + px];
            hp0[k] = pk2(h0v, h0v); hp1[k] = pk2(h1v, h1v); hp2[k] = pk2(h2v, h2v);
        }
        int n0 = nidxS[0 * PXB + px], n1 = nidxS[1 * PXB + px], n2 = nidxS[2 * PXB + px];
        const ulonglong2* fr0 = (const ulonglong2*)(g_featT + ((size_t)(b * NP + n0) << 6));
        const ulonglong2* fr1 = (const ulonglong2*)(g_featT + ((size_t)(b * NP + n1) << 6));
        const ulonglong2* fr2 = (const ulonglong2*)(g_featT + ((size_t)(b * NP + n2) << 6));
        const int c8lo = half * 8;
        #pragma unroll
        for (int cc = 0; cc < 8; ++cc) {
            int c8 = c8lo + cc;
            int c2 = 2 * c8;
            ull wa0 = w2a2[c2],   wb0 = w2b2[c2],   wc0 = w2c2[c2],   bb0 = b2p2[c2];
            ull wa1 = w2a2[c2+1], wb1 = w2b2[c2+1], wc1 = w2c2[c2+1], bb1 = b2p2[c2+1];
            ulonglong2 fA = fr0[c8], fB = fr1[c8], fC = fr2[c8];
            ull u0 = 0ull, u1 = 0ull;
            #pragma unroll
            for (int k = 0; k < 3; ++k) {
                ulonglong2 f = (k == 0) ? fA : (k == 1) ? fB : fC;
                ull z0 = fma2_(wc0, hp2[k], fma2_(wb0, hp1[k], fma2_(wa0, hp0[k], bb0)));
                ull z1 = fma2_(wc1, hp2[k], fma2_(wb1, hp1[k], fma2_(wa1, hp0[k], bb1)));
                z0 = mul2_(z0, HALF2); z1 = mul2_(z1, HALF2);
                float za, zb, zc, zd;
                upk2(za, zb, z0); upk2(zc, zd, z1);
                float sa = __fmaf_rn(0.5f, tanh_ap(za), 0.5f);
                float sb = __fmaf_rn(0.5f, tanh_ap(zb), 0.5f);
                float sc = __fmaf_rn(0.5f, tanh_ap(zc), 0.5f);
                float sd = __fmaf_rn(0.5f, tanh_ap(zd), 0.5f);
                u0 = fma2_(pk2(sa, sb), f.x, u0);
                u1 = fma2_(pk2(sc, sd), f.y, u1);
            }
            float v0, v1, v2, v3;
            upk2(v0, v1, u0); upk2(v2, v3, u1);
            int cb = 4 * c8;
            fin_s[(cb + 0) * PXB + px] = v0;
            fin_s[(cb + 1) * PXB + px] = v1;
            fin_s[(cb + 2) * PXB + px] = v2;
            fin_s[(cb + 3) * PXB + px] = v3;
        }
    }
    __syncthreads();

    // ---- Phase 3: block GEMM, each thread 8px x 4co ----
    const int p0 = 8 * (tid & 15);
    const int c0 = 4 * (tid >> 4);
    ull acc[8][2];
    #pragma unroll
    for (int p = 0; p < 8; ++p) { acc[p][0] = 0ull; acc[p][1] = 0ull; }

    #pragma unroll 4
    for (int c = 0; c < CH; ++c) {
        const float4* frp = (const float4*)(fin_s + c * PXB + p0);
        float4 fA = frp[0], fB = frp[1];
        float4 wv = *(const float4*)(woutT_s + c * CH + c0);
        ull w01 = pk2(wv.x, wv.y), w23 = pk2(wv.z, wv.w);
        ull fp;
        fp = pk2(fA.x, fA.x); acc[0][0]=fma2_(w01,fp,acc[0][0]); acc[0][1]=fma2_(w23,fp,acc[0][1]);
        fp = pk2(fA.y, fA.y); acc[1][0]=fma2_(w01,fp,acc[1][0]); acc[1][1]=fma2_(w23,fp,acc[1][1]);
        fp = pk2(fA.z, fA.z); acc[2][0]=fma2_(w01,fp,acc[2][0]); acc[2][1]=fma2_(w23,fp,acc[2][1]);
        fp = pk2(fA.w, fA.w); acc[3][0]=fma2_(w01,fp,acc[3][0]); acc[3][1]=fma2_(w23,fp,acc[3][1]);
        fp = pk2(fB.x, fB.x); acc[4][0]=fma2_(w01,fp,acc[4][0]); acc[4][1]=fma2_(w23,fp,acc[4][1]);
        fp = pk2(fB.y, fB.y); acc[5][0]=fma2_(w01,fp,acc[5][0]); acc[5][1]=fma2_(w23,fp,acc[5][1]);
        fp = pk2(fB.z, fB.z); acc[6][0]=fma2_(w01,fp,acc[6][0]); acc[6][1]=fma2_(w23,fp,acc[6][1]);
        fp = pk2(fB.w, fB.w); acc[7][0]=fma2_(w01,fp,acc[7][0]); acc[7][1]=fma2_(w23,fp,acc[7][1]);
    }

    {
        const int m   = tid & 15;
        const int row = m >> 1, colb = (m & 1) * 8;
        const int q0  = (blockIdx.y * 8 + row) * IMW + blockIdx.x * 16 + colb;
        float* outb = out + ((size_t)b * CH) * QPB + q0;
        #pragma unroll
        for (int j = 0; j < 2; ++j) {
            float lo[8], hi[8];
            #pragma unroll
            for (int p = 0; p < 8; ++p) upk2(lo[p], hi[p], acc[p][j]);
            int coA = c0 + 2 * j, coB = coA + 1;
            float bA = boutF[coA], bB = boutF[coB];
            #pragma unroll
            for (int p = 0; p < 8; ++p) {
                lo[p] += bA; lo[p] = (lo[p] >= 0.f) ? lo[p] : 0.1f * lo[p];
                hi[p] += bB; hi[p] = (hi[p] >= 0.f) ? hi[p] : 0.1f * hi[p];
            }
            float* oA = outb + (size_t)coA * QPB;
            float* oB = outb + (size_t)coB * QPB;
            *(float4*)(oA)     = make_float4(lo[0], lo[1], lo[2], lo[3]);
            *(float4*)(oA + 4) = make_float4(lo[4], lo[5], lo[6], lo[7]);
            *(float4*)(oB)     = make_float4(hi[0], hi[1], hi[2], hi[3]);
            *(float4*)(oB + 4) = make_float4(hi[4], hi[5], hi[6], hi[7]);
        }
    }
}

extern "C" void kernel_launch(void* const* d_in, const int* in_sizes, int n_in,
                              void* d_out, int out_size) {
    const float* uv    = (const float*)d_in[0];
    const float* feat  = (const float*)d_in[1];
    const float* w1    = (const float*)d_in[4];
    const float* b1    = (const float*)d_in[5];
    const float* w2    = (const float*)d_in[6];
    const float* b2    = (const float*)d_in[7];
    const float* w_out = (const float*)d_in[8];
    const float* b_out = (const float*)d_in[9];
    float* out = (float*)d_out;

    k_prep<<<BS + BS * 64 + 1, 512>>>(uv, feat, w_out);

    cudaFuncSetAttribute(k_main, cudaFuncAttributeMaxDynamicSharedMemorySize, SMEM_BYTES);
    dim3 grid(IMW / 16, IMH / 8, BS);
    k_main<<<grid, TPB, SMEM_BYTES>>>(w1, b1, w2, b2, b_out, out);
}

// round 14
// speedup vs baseline: 1.2253x; 1.2253x over previous
#include <cuda_runtime.h>
#include <math.h>

#define BS   2
#define NP   4096
#define CH   64
#define IMH  128
#define IMW  256
#define QPB  (IMH*IMW)
#define TPB  128
#define PXB  128
#define BSZ  8
#define NBX  (IMW/BSZ)
#define NBY  (IMH/BSZ)
#define NBINS (NBX*NBY)
#define CAND_MAX 384
#define CPAD (CAND_MAX + 8)        // 392
#define UMAX 64
#define FPAD 68                    // featRow stride (floats), bank-spread pad

typedef unsigned long long ull;

__device__ float  g_featT[BS * NP * CH];    // [b][point][channel]
__device__ float  g_woutT[CH * CH];         // [cin][cout]
__device__ float4 g_binned[BS * NP];        // (px, py, psq, idx-as-float)
__device__ int    g_prefix[BS * (NBINS + 1)];

__device__ __forceinline__ ull pk2(float lo, float hi) {
    ull r; asm("mov.b64 %0,{%1,%2};" : "=l"(r) : "f"(lo), "f"(hi)); return r;
}
__device__ __forceinline__ void upk2(float& lo, float& hi, ull v) {
    asm("mov.b64 {%0,%1},%2;" : "=f"(lo), "=f"(hi) : "l"(v));
}
__device__ __forceinline__ ull fma2_(ull a, ull b, ull c) {
    ull d; asm("fma.rn.f32x2 %0,%1,%2,%3;" : "=l"(d) : "l"(a), "l"(b), "l"(c)); return d;
}
__device__ __forceinline__ ull mul2_(ull a, ull b) {
    ull d; asm("mul.rn.f32x2 %0,%1,%2;" : "=l"(d) : "l"(a), "l"(b)); return d;
}
__device__ __forceinline__ ull add2_(ull a, ull b) {
    ull d; asm("add.rn.f32x2 %0,%1,%2;" : "=l"(d) : "l"(a), "l"(b)); return d;
}
__device__ __forceinline__ ull sub2_(ull a, ull b) {
    ull d; asm("sub.rn.f32x2 %0,%1,%2;" : "=l"(d) : "l"(a), "l"(b)); return d;
}
__device__ __forceinline__ float tanh_ap(float x) {
    float y; asm("tanh.approx.f32 %0,%1;" : "=f"(y) : "f"(x)); return y;
}

// ============================================================================
// k_prep: unchanged from R8 — bins, feature transpose, w_out transpose.
// ============================================================================
__global__ __launch_bounds__(512, 1)
void k_prep(const float* __restrict__ uv, const float* __restrict__ feat,
            const float* __restrict__ w_out) {
    __shared__ int s_cnt[NBINS];
    __shared__ int s_pfx[NBINS];
    __shared__ float s_tile[64][65];
    const int t = threadIdx.x;
    const int bid = blockIdx.x;

    if (bid < BS) {
        const int b = bid;
        s_cnt[t] = 0;
        __syncthreads();
        const float* uvb = uv + b * 2 * NP;
        float4 myp[8]; int mybin[8];
        #pragma unroll
        for (int r = 0; r < 8; ++r) {
            int i = t + r * 512;
            float px = uvb[i], py = uvb[NP + i];
            float psq = __fadd_rn(__fmul_rn(px, px), __fmul_rn(py, py));
            int bx = min(max((int)(px * (1.0f / BSZ)), 0), NBX - 1);
            int by = min(max((int)(py * (1.0f / BSZ)), 0), NBY - 1);
            mybin[r] = by * NBX + bx;
            myp[r] = make_float4(px, py, psq, __int_as_float(i));
            atomicAdd(&s_cnt[mybin[r]], 1);
        }
        __syncthreads();
        int v = s_cnt[t];
        s_pfx[t] = v;
        __syncthreads();
        for (int d = 1; d < NBINS; d <<= 1) {
            int add = (t >= d) ? s_pfx[t - d] : 0;
            __syncthreads();
            s_pfx[t] += add;
            __syncthreads();
        }
        g_prefix[b * (NBINS + 1) + t + 1] = s_pfx[t];
        if (t == 0) g_prefix[b * (NBINS + 1)] = 0;
        s_cnt[t] = s_pfx[t] - v;
        __syncthreads();
        #pragma unroll
        for (int r = 0; r < 8; ++r) {
            int pos = atomicAdd(&s_cnt[mybin[r]], 1);
            g_binned[b * NP + pos] = myp[r];
        }
    } else if (bid < BS + BS * 64) {
        int tb = bid - BS;
        int b  = tb >> 6;
        int i0 = (tb & 63) * 64;
        int c  = t >> 3, j = t & 7;
        #pragma unroll
        for (int rep = 0; rep < 2; ++rep) {
            int i4 = j + rep * 8;
            float4 v = *(const float4*)(feat + ((size_t)(b * CH + c) * NP + i0 + i4 * 4));
            s_tile[i4 * 4 + 0][c] = v.x;
            s_tile[i4 * 4 + 1][c] = v.y;
            s_tile[i4 * 4 + 2][c] = v.z;
            s_tile[i4 * 4 + 3][c] = v.w;
        }
        __syncthreads();
        int i = t >> 3;
        #pragma unroll
        for (int rep = 0; rep < 2; ++rep) {
            int c4 = j + rep * 8;
            float4 w;
            w.x = s_tile[i][c4 * 4 + 0];
            w.y = s_tile[i][c4 * 4 + 1];
            w.z = s_tile[i][c4 * 4 + 2];
            w.w = s_tile[i][c4 * 4 + 3];
            *(float4*)(g_featT + ((size_t)(b * NP + i0 + i) << 6) + c4 * 4) = w;
        }
    } else {
        int c = t >> 3, j = t & 7;
        #pragma unroll
        for (int rep = 0; rep < 2; ++rep) {
            int i4 = j + rep * 8;
            float4 v = *(const float4*)(w_out + (size_t)c * CH + i4 * 4);
            s_tile[i4 * 4 + 0][c] = v.x;
            s_tile[i4 * 4 + 1][c] = v.y;
            s_tile[i4 * 4 + 2][c] = v.z;
            s_tile[i4 * 4 + 3][c] = v.w;
        }
        __syncthreads();
        int i = t >> 3;
        #pragma unroll
        for (int rep = 0; rep < 2; ++rep) {
            int c4 = j + rep * 8;
            float4 w;
            w.x = s_tile[i][c4 * 4 + 0];
            w.y = s_tile[i][c4 * 4 + 1];
            w.z = s_tile[i][c4 * 4 + 2];
            w.w = s_tile[i][c4 * 4 + 3];
            *(float4*)(g_woutT + (size_t)i * CH + c4 * 4) = w;
        }
    }
}

#define INSERT(dd, pi, sl) {                                                   \
    if ((dd) < d2b || ((dd) == d2b && (pi) < i2)) {                            \
        if ((dd) < d1 || ((dd) == d1 && (pi) < i1)) {                          \
            d2b = d1; i2 = i1; s2 = s1;                                        \
            if ((dd) < d0 || ((dd) == d0 && (pi) < i0))                        \
                 { d1 = d0; i1 = i0; s1 = s0; d0 = (dd); i0 = (pi); s0 = (sl); } \
            else { d1 = (dd); i1 = (pi); s1 = (sl); }                          \
        } else { d2b = (dd); i2 = (pi); s2 = (sl); }                           \
    } }

// SMEM layout (floats):
//  consts [0,352) | featRows [352, 352+64*68) | UNION at 4704:
//    { candPx/Py/Psq/Idx (4*392) + claim(392) + map(392) }  OR  fin[64*128]
#define SM_W2A   0
#define SM_W2B   64
#define SM_W2C   128
#define SM_B2    192
#define SM_BOUT  256
#define SM_W1    320
#define SM_B1    336
#define SM_FEAT  352
#define SM_UNION (SM_FEAT + UMAX * FPAD)     // 352 + 4352 = 4704
#define SM_PX    SM_UNION
#define SM_PY    (SM_PX + CPAD)
#define SM_PSQ   (SM_PY + CPAD)
#define SM_IDX   (SM_PSQ + CPAD)
#define SM_CLAIM (SM_IDX + CPAD)
#define SM_MAP   (SM_CLAIM + CPAD)
#define SM_FIN   SM_UNION
#define SMEM_FLOATS (SM_UNION + CH * PXB)    // 4704 + 8192 = 12896
#define SMEM_BYTES  (SMEM_FLOATS * 4)        // 51584

__global__ __launch_bounds__(TPB, 4)
void k_main(const float* __restrict__ w1, const float* __restrict__ b1,
            const float* __restrict__ w2, const float* __restrict__ b2,
            const float* __restrict__ b_out,
            float* __restrict__ out)
{
    extern __shared__ float sm[];
    float* featR   = sm + SM_FEAT;
    float* candPx  = sm + SM_PX;
    float* candPy  = sm + SM_PY;
    float* candPsq = sm + SM_PSQ;
    int*   candIdx = (int*)(sm + SM_IDX);
    int*   claimA  = (int*)(sm + SM_CLAIM);
    int*   mapA    = (int*)(sm + SM_MAP);
    float* fin_s   = sm + SM_FIN;
    float* w2aF = sm + SM_W2A; float* w2bF = sm + SM_W2B; float* w2cF = sm + SM_W2C;
    float* b2F  = sm + SM_B2;  float* boutF = sm + SM_BOUT;
    float* w1s = sm + SM_W1;   float* b1s = sm + SM_B1;
    __shared__ int s_startA[3], s_cntA[3], s_offA[3], s_totalA;
    __shared__ int uniqIdx[UMAX];
    __shared__ int sh_ucnt;

    const int tid = threadIdx.x;
    const int b   = blockIdx.z;
    const int tx  = tid & 15, ty = tid >> 4;       // 16x8 pixel tile
    const int gxi = blockIdx.x * 16 + tx;
    const int gyi = blockIdx.y * 8 + ty;
    const float gx = (float)gxi, gy = (float)gyi;
    const float qsq = gx * gx + gy * gy;           // exact for integer coords

    // candidate ring: 4x3 bins
    const int tbx0 = blockIdx.x * 2;
    const int tby0 = blockIdx.y;
    const int bxlo = max(tbx0 - 1, 0), bxhi = min(tbx0 + 2, NBX - 1);
    const int bylo = max(tby0 - 1, 0), byhi = min(tby0 + 1, NBY - 1);
    const int nrows = byhi - bylo + 1;

    if (tid < nrows) {
        int row = bylo + tid;
        int s = g_prefix[b * (NBINS + 1) + row * NBX + bxlo];
        int e = g_prefix[b * (NBINS + 1) + row * NBX + bxhi + 1];
        s_startA[tid] = s; s_cntA[tid] = e - s;
    }
    for (int i = tid; i < CAND_MAX; i += TPB) claimA[i] = 0;
    if (tid == 0) sh_ucnt = 0;
    if (tid < CH) {
        w2aF[tid] = w2[tid * 3 + 0];
        w2bF[tid] = w2[tid * 3 + 1];
        w2cF[tid] = w2[tid * 3 + 2];
        b2F[tid]  = b2[tid];
        boutF[tid] = b_out[tid];
    }
    if (tid < 9) w1s[tid] = w1[tid];
    if (tid < 3) b1s[tid] = b1[tid];
    __syncthreads();
    if (tid == 0) {
        int off = 0;
        for (int r = 0; r < nrows; ++r) { s_offA[r] = off; off += s_cntA[r]; }
        s_totalA = off;
    }
    __syncthreads();
    const int total = s_totalA;
    const bool ovf = total > CAND_MAX;
    if (!ovf) {
        for (int r = 0; r < nrows; ++r) {
            int c = s_cntA[r], st = s_startA[r], of = s_offA[r];
            for (int i = tid; i < c; i += TPB) {
                float4 p = g_binned[b * NP + st + i];
                candPx[of + i] = p.x; candPy[of + i] = p.y;
                candPsq[of + i] = p.z; candIdx[of + i] = __float_as_int(p.w);
            }
        }
        if (tid < 8) {
            candPx[total + tid] = 0.f; candPy[total + tid] = 0.f;
            candPsq[total + tid] = 1e30f; candIdx[total + tid] = 0x7ffffff0;
        }
    }
    __syncthreads();

    // ---- Phase 1: KNN, 4 candidates/iter via LDS.128 (as R8) ----
    float d0 = INFINITY, d1 = INFINITY, d2b = INFINITY;
    int   i0 = 0x7fffffff, i1 = 0x7fffffff, i2 = 0x7fffffff;
    int   s0 = 0, s1 = 0, s2 = 0;
    bool  fb = false;
    if (!ovf) {
        const float4* px4  = (const float4*)candPx;
        const float4* py4  = (const float4*)candPy;
        const float4* psq4 = (const float4*)candPsq;
        const ull gx2 = pk2(gx, gx), gy2 = pk2(gy, gy), qsq2 = pk2(qsq, qsq);
        int nq = (total + 3) >> 2;
        #pragma unroll 2
        for (int jq = 0; jq < nq; ++jq) {
            float4 PX = px4[jq], PY = py4[jq], PSQ = psq4[jq];
            ull crA = fma2_(pk2(PY.x, PY.y), gy2, mul2_(pk2(PX.x, PX.y), gx2));
            ull ddA = sub2_(add2_(qsq2, pk2(PSQ.x, PSQ.y)), add2_(crA, crA));
            ull crB = fma2_(pk2(PY.z, PY.w), gy2, mul2_(pk2(PX.z, PX.w), gx2));
            ull ddB = sub2_(add2_(qsq2, pk2(PSQ.z, PSQ.w)), add2_(crB, crB));
            float a0, a1, a2, a3;
            upk2(a0, a1, ddA); upk2(a2, a3, ddB);
            int base = 4 * jq;
            if (a0 <= d2b) { int pi = candIdx[base + 0]; INSERT(a0, pi, base + 0); }
            if (a1 <= d2b) { int pi = candIdx[base + 1]; INSERT(a1, pi, base + 1); }
            if (a2 <= d2b) { int pi = candIdx[base + 2]; INSERT(a2, pi, base + 2); }
            if (a3 <= d2b) { int pi = candIdx[base + 3]; INSERT(a3, pi, base + 3); }
        }
    }
    // completeness: any excluded point is >= dmin away
    float dl = (bxlo > 0)       ? (gx - (float)(bxlo * BSZ))       : 1e9f;
    float dr = (bxhi < NBX - 1) ? ((float)((bxhi + 1) * BSZ) - gx) : 1e9f;
    float dt = (bylo > 0)       ? (gy - (float)(bylo * BSZ))       : 1e9f;
    float db = (byhi < NBY - 1) ? ((float)((byhi + 1) * BSZ) - gy) : 1e9f;
    float dmin = fminf(fminf(dl, dr), fminf(dt, db));
    if (ovf || !(d2b + 0.25f <= dmin * dmin)) {    // rare exact fallback
        fb = true;
        d0 = d1 = d2b = INFINITY; i0 = i1 = i2 = 0x7fffffff;
        const float4* gp = g_binned + b * NP;
        #pragma unroll 4
        for (int j = 0; j < NP; ++j) {
            float4 p = gp[j];
            float cr = __fmaf_rn(p.y, gy, __fmul_rn(p.x, gx));
            float dd = __fsub_rn(__fadd_rn(qsq, p.z), __fadd_rn(cr, cr));
            if (dd <= d2b) { int pi = __float_as_int(p.w); INSERT(dd, pi, j); }
        }
    }

    // ---- Geometry -> h (registers, as R8) ----
    int nidx[3] = { i0, i1, i2 };
    int nsl[3]  = { s0, s1, s2 };
    ull hp0[3], hp1[3], hp2[3];
    #pragma unroll
    for (int k = 0; k < 3; ++k) {
        float pxx, pyy;
        if (!fb) { pxx = candPx[nsl[k]]; pyy = candPy[nsl[k]]; }
        else     { float4 p = g_binned[b * NP + nsl[k]]; pxx = p.x; pyy = p.y; }
        float dx = __fsub_rn(pxx, gx);
        float dy = __fsub_rn(pyy, gy);
        float nrm = __fsqrt_rn(__fadd_rn(__fmul_rn(dx, dx), __fmul_rn(dy, dy)));
        float h[3];
        #pragma unroll
        for (int j = 0; j < 3; ++j) {
            float t = __fmaf_rn(w1s[j*3+2], nrm,
                      __fmaf_rn(w1s[j*3+1], dy, __fmul_rn(w1s[j*3+0], dx)));
            t = t + b1s[j];
            h[j] = (t >= 0.f) ? t : 0.1f * t;
        }
        hp0[k] = pk2(h[0], h[0]); hp1[k] = pk2(h[1], h[1]); hp2[k] = pk2(h[2], h[2]);
    }

    // ---- Unique-neighbor dedup: claim slots, compact, coalesced row load ----
    if (!fb && !ovf) {
        #pragma unroll
        for (int k = 0; k < 3; ++k) {
            int s = nsl[k];
            if (atomicExch(&claimA[s], 1) == 0) {
                int u = atomicAdd(&sh_ucnt, 1);
                if (u < UMAX) { uniqIdx[u] = nidx[k]; mapA[s] = u; }
                else          { mapA[s] = -1; }
            }
        }
    }
    __syncthreads();
    int u0 = -1, u1 = -1, u2 = -1;
    if (!fb && !ovf) { u0 = mapA[nsl[0]]; u1 = mapA[nsl[1]]; u2 = mapA[nsl[2]]; }
    {
        int ucount = min(sh_ucnt, UMAX);
        for (int i = tid; i < ucount * 16; i += TPB) {
            int u = i >> 4, c4 = i & 15;
            float4 v = ((const float4*)(g_featT + ((size_t)(b * NP + uniqIdx[u]) << 6)))[c4];
            ((float4*)(featR + u * FPAD))[c4] = v;
        }
    }
    __syncthreads();   // featRows ready; cand/claim/map dead -> fin may overwrite

    // ---- Phase 2: score + gather (features from SMEM rows) -> fin_s ----
    {
        const ull HALF2 = 0x3F0000003F000000ULL;
        const ull* w2a2 = (const ull*)w2aF;
        const ull* w2b2 = (const ull*)w2bF;
        const ull* w2c2 = (const ull*)w2cF;
        const ull* b2p2 = (const ull*)b2F;
        const ulonglong2* fr0 = (const ulonglong2*)(g_featT + ((size_t)(b * NP + nidx[0]) << 6));
        const ulonglong2* fr1 = (const ulonglong2*)(g_featT + ((size_t)(b * NP + nidx[1]) << 6));
        const ulonglong2* fr2 = (const ulonglong2*)(g_featT + ((size_t)(b * NP + nidx[2]) << 6));
        #pragma unroll 4
        for (int c8 = 0; c8 < 16; ++c8) {
            int c2 = 2 * c8;
            ull wa0 = w2a2[c2],   wb0 = w2b2[c2],   wc0 = w2c2[c2],   bb0 = b2p2[c2];
            ull wa1 = w2a2[c2+1], wb1 = w2b2[c2+1], wc1 = w2c2[c2+1], bb1 = b2p2[c2+1];
            ulonglong2 fA = (u0 >= 0) ? *(const ulonglong2*)(featR + u0 * FPAD + c8 * 4) : fr0[c8];
            ulonglong2 fB = (u1 >= 0) ? *(const ulonglong2*)(featR + u1 * FPAD + c8 * 4) : fr1[c8];
            ulonglong2 fC = (u2 >= 0) ? *(const ulonglong2*)(featR + u2 * FPAD + c8 * 4) : fr2[c8];
            ull uacc0 = 0ull, uacc1 = 0ull;
            #pragma unroll
            for (int k = 0; k < 3; ++k) {
                ulonglong2 f = (k == 0) ? fA : (k == 1) ? fB : fC;
                ull z0 = fma2_(wc0, hp2[k], fma2_(wb0, hp1[k], fma2_(wa0, hp0[k], bb0)));
                ull z1 = fma2_(wc1, hp2[k], fma2_(wb1, hp1[k], fma2_(wa1, hp0[k], bb1)));
                z0 = mul2_(z0, HALF2); z1 = mul2_(z1, HALF2);
                float za, zb, zc, zd;
                upk2(za, zb, z0); upk2(zc, zd, z1);
                float sa = __fmaf_rn(0.5f, tanh_ap(za), 0.5f);
                float sb = __fmaf_rn(0.5f, tanh_ap(zb), 0.5f);
                float sc = __fmaf_rn(0.5f, tanh_ap(zc), 0.5f);
                float sd = __fmaf_rn(0.5f, tanh_ap(zd), 0.5f);
                uacc0 = fma2_(pk2(sa, sb), f.x, uacc0);
                uacc1 = fma2_(pk2(sc, sd), f.y, uacc1);
            }
            float v0, v1, v2, v3;
            upk2(v0, v1, uacc0); upk2(v2, v3, uacc1);
            int cb = 4 * c8;
            fin_s[(cb + 0) * PXB + tid] = v0;
            fin_s[(cb + 1) * PXB + tid] = v1;
            fin_s[(cb + 2) * PXB + tid] = v2;
            fin_s[(cb + 3) * PXB + tid] = v3;
        }
    }
    __syncthreads();

    // ---- Phase 3: block GEMM 128px x 64co, thread = 8px x 8co (as R8);
    //      weights from g_woutT via uniform LDG.128 (L1-resident) ----
    const int p0 = 8 * (tid & 15);
    const int c0 = 8 * (tid >> 4);
    ull acc[8][4];
    #pragma unroll
    for (int p = 0; p < 8; ++p)
        #pragma unroll
        for (int j = 0; j < 4; ++j) acc[p][j] = 0ull;

    #pragma unroll 4
    for (int c = 0; c < CH; ++c) {
        const float4* frp = (const float4*)(fin_s + c * PXB + p0);
        float4 fA = frp[0], fB = frp[1];
        const ulonglong2* wg = (const ulonglong2*)(g_woutT + c * CH + c0);
        ulonglong2 w01 = wg[0], w23 = wg[1];
        ull fp;
        fp = pk2(fA.x, fA.x);
        acc[0][0]=fma2_(w01.x,fp,acc[0][0]); acc[0][1]=fma2_(w01.y,fp,acc[0][1]);
        acc[0][2]=fma2_(w23.x,fp,acc[0][2]); acc[0][3]=fma2_(w23.y,fp,acc[0][3]);
        fp = pk2(fA.y, fA.y);
        acc[1][0]=fma2_(w01.x,fp,acc[1][0]); acc[1][1]=fma2_(w01.y,fp,acc[1][1]);
        acc[1][2]=fma2_(w23.x,fp,acc[1][2]); acc[1][3]=fma2_(w23.y,fp,acc[1][3]);
        fp = pk2(fA.z, fA.z);
        acc[2][0]=fma2_(w01.x,fp,acc[2][0]); acc[2][1]=fma2_(w01.y,fp,acc[2][1]);
        acc[2][2]=fma2_(w23.x,fp,acc[2][2]); acc[2][3]=fma2_(w23.y,fp,acc[2][3]);
        fp = pk2(fA.w, fA.w);
        acc[3][0]=fma2_(w01.x,fp,acc[3][0]); acc[3][1]=fma2_(w01.y,fp,acc[3][1]);
        acc[3][2]=fma2_(w23.x,fp,acc[3][2]); acc[3][3]=fma2_(w23.y,fp,acc[3][3]);
        fp = pk2(fB.x, fB.x);
        acc[4][0]=fma2_(w01.x,fp,acc[4][0]); acc[4][1]=fma2_(w01.y,fp,acc[4][1]);
        acc[4][2]=fma2_(w23.x,fp,acc[4][2]); acc[4][3]=fma2_(w23.y,fp,acc[4][3]);
        fp = pk2(fB.y, fB.y);
        acc[5][0]=fma2_(w01.x,fp,acc[5][0]); acc[5][1]=fma2_(w01.y,fp,acc[5][1]);
        acc[5][2]=fma2_(w23.x,fp,acc[5][2]); acc[5][3]=fma2_(w23.y,fp,acc[5][3]);
        fp = pk2(fB.z, fB.z);
        acc[6][0]=fma2_(w01.x,fp,acc[6][0]); acc[6][1]=fma2_(w01.y,fp,acc[6][1]);
        acc[6][2]=fma2_(w23.x,fp,acc[6][2]); acc[6][3]=fma2_(w23.y,fp,acc[6][3]);
        fp = pk2(fB.w, fB.w);
        acc[7][0]=fma2_(w01.x,fp,acc[7][0]); acc[7][1]=fma2_(w01.y,fp,acc[7][1]);
        acc[7][2]=fma2_(w23.x,fp,acc[7][2]); acc[7][3]=fma2_(w23.y,fp,acc[7][3]);
    }

    // epilogue: bias + leaky, 8 contiguous px per co -> STG.128
    {
        const int m   = tid & 15;
        const int row = m >> 1, colb = (m & 1) * 8;
        const int q0  = (blockIdx.y * 8 + row) * IMW + blockIdx.x * 16 + colb;
        float* outb = out + ((size_t)b * CH) * QPB + q0;
        #pragma unroll
        for (int j = 0; j < 4; ++j) {
            float lo[8], hi[8];
            #pragma unroll
            for (int p = 0; p < 8; ++p) upk2(lo[p], hi[p], acc[p][j]);
            int coA = c0 + 2 * j, coB = coA + 1;
            float bA = boutF[coA], bB = boutF[coB];
            #pragma unroll
            for (int p = 0; p < 8; ++p) {
                lo[p] += bA; lo[p] = (lo[p] >= 0.f) ? lo[p] : 0.1f * lo[p];
                hi[p] += bB; hi[p] = (hi[p] >= 0.f) ? hi[p] : 0.1f * hi[p];
            }
            float* oA = outb + (size_t)coA * QPB;
            float* oB = outb + (size_t)coB * QPB;
            *(float4*)(oA)     = make_float4(lo[0], lo[1], lo[2], lo[3]);
            *(float4*)(oA + 4) = make_float4(lo[4], lo[5], lo[6], lo[7]);
            *(float4*)(oB)     = make_float4(hi[0], hi[1], hi[2], hi[3]);
            *(float4*)(oB + 4) = make_float4(hi[4], hi[5], hi[6], hi[7]);
        }
    }
}

extern "C" void kernel_launch(void* const* d_in, const int* in_sizes, int n_in,
                              void* d_out, int out_size) {
    const float* uv    = (const float*)d_in[0];
    const float* feat  = (const float*)d_in[1];
    const float* w1    = (const float*)d_in[4];
    const float* b1    = (const float*)d_in[5];
    const float* w2    = (const float*)d_in[6];
    const float* b2    = (const float*)d_in[7];
    const float* w_out = (const float*)d_in[8];
    const float* b_out = (const float*)d_in[9];
    float* out = (float*)d_out;

    k_prep<<<BS + BS * 64 + 1, 512>>>(uv, feat, w_out);

    cudaFuncSetAttribute(k_main, cudaFuncAttributeMaxDynamicSharedMemorySize, SMEM_BYTES);
    dim3 grid(IMW / 16, IMH / 8, BS);
    k_main<<<grid, TPB, SMEM_BYTES>>>(w1, b1, w2, b2, b_out, out);
}

// round 15
// speedup vs baseline: 1.2648x; 1.0322x over previous
#include <cuda_runtime.h>
#include <math.h>

#define BS   2
#define NP   4096
#define CH   64
#define IMH  128
#define IMW  256
#define QPB  (IMH*IMW)
#define TPB  64
#define PXB  64
#define BSZ  8
#define NBX  (IMW/BSZ)
#define NBY  (IMH/BSZ)
#define NBINS (NBX*NBY)
#define CAND_MAX 256
#define CPAD (CAND_MAX + 8)        // 264
#define UMAX 48
#define FPAD 68                    // featRow stride (floats)

typedef unsigned long long ull;

__device__ float  g_featT[BS * NP * CH];    // [b][point][channel]
__device__ float  g_woutT[CH * CH];         // [cin][cout]
__device__ float4 g_binned[BS * NP];        // (px, py, psq, idx-as-float)
__device__ int    g_prefix[BS * (NBINS + 1)];

__device__ __forceinline__ ull pk2(float lo, float hi) {
    ull r; asm("mov.b64 %0,{%1,%2};" : "=l"(r) : "f"(lo), "f"(hi)); return r;
}
__device__ __forceinline__ void upk2(float& lo, float& hi, ull v) {
    asm("mov.b64 {%0,%1},%2;" : "=f"(lo), "=f"(hi) : "l"(v));
}
__device__ __forceinline__ ull fma2_(ull a, ull b, ull c) {
    ull d; asm("fma.rn.f32x2 %0,%1,%2,%3;" : "=l"(d) : "l"(a), "l"(b), "l"(c)); return d;
}
__device__ __forceinline__ ull mul2_(ull a, ull b) {
    ull d; asm("mul.rn.f32x2 %0,%1,%2;" : "=l"(d) : "l"(a), "l"(b)); return d;
}
__device__ __forceinline__ ull add2_(ull a, ull b) {
    ull d; asm("add.rn.f32x2 %0,%1,%2;" : "=l"(d) : "l"(a), "l"(b)); return d;
}
__device__ __forceinline__ ull sub2_(ull a, ull b) {
    ull d; asm("sub.rn.f32x2 %0,%1,%2;" : "=l"(d) : "l"(a), "l"(b)); return d;
}
__device__ __forceinline__ float tanh_ap(float x) {
    float y; asm("tanh.approx.f32 %0,%1;" : "=f"(y) : "f"(x)); return y;
}

// ============================================================================
// k_prep: unchanged — bins, feature transpose, w_out transpose.
// ============================================================================
__global__ __launch_bounds__(512, 1)
void k_prep(const float* __restrict__ uv, const float* __restrict__ feat,
            const float* __restrict__ w_out) {
    __shared__ int s_cnt[NBINS];
    __shared__ int s_pfx[NBINS];
    __shared__ float s_tile[64][65];
    const int t = threadIdx.x;
    const int bid = blockIdx.x;

    if (bid < BS) {
        const int b = bid;
        s_cnt[t] = 0;
        __syncthreads();
        const float* uvb = uv + b * 2 * NP;
        float4 myp[8]; int mybin[8];
        #pragma unroll
        for (int r = 0; r < 8; ++r) {
            int i = t + r * 512;
            float px = uvb[i], py = uvb[NP + i];
            float psq = __fadd_rn(__fmul_rn(px, px), __fmul_rn(py, py));
            int bx = min(max((int)(px * (1.0f / BSZ)), 0), NBX - 1);
            int by = min(max((int)(py * (1.0f / BSZ)), 0), NBY - 1);
            mybin[r] = by * NBX + bx;
            myp[r] = make_float4(px, py, psq, __int_as_float(i));
            atomicAdd(&s_cnt[mybin[r]], 1);
        }
        __syncthreads();
        int v = s_cnt[t];
        s_pfx[t] = v;
        __syncthreads();
        for (int d = 1; d < NBINS; d <<= 1) {
            int add = (t >= d) ? s_pfx[t - d] : 0;
            __syncthreads();
            s_pfx[t] += add;
            __syncthreads();
        }
        g_prefix[b * (NBINS + 1) + t + 1] = s_pfx[t];
        if (t == 0) g_prefix[b * (NBINS + 1)] = 0;
        s_cnt[t] = s_pfx[t] - v;
        __syncthreads();
        #pragma unroll
        for (int r = 0; r < 8; ++r) {
            int pos = atomicAdd(&s_cnt[mybin[r]], 1);
            g_binned[b * NP + pos] = myp[r];
        }
    } else if (bid < BS + BS * 64) {
        int tb = bid - BS;
        int b  = tb >> 6;
        int i0 = (tb & 63) * 64;
        int c  = t >> 3, j = t & 7;
        #pragma unroll
        for (int rep = 0; rep < 2; ++rep) {
            int i4 = j + rep * 8;
            float4 v = *(const float4*)(feat + ((size_t)(b * CH + c) * NP + i0 + i4 * 4));
            s_tile[i4 * 4 + 0][c] = v.x;
            s_tile[i4 * 4 + 1][c] = v.y;
            s_tile[i4 * 4 + 2][c] = v.z;
            s_tile[i4 * 4 + 3][c] = v.w;
        }
        __syncthreads();
        int i = t >> 3;
        #pragma unroll
        for (int rep = 0; rep < 2; ++rep) {
            int c4 = j + rep * 8;
            float4 w;
            w.x = s_tile[i][c4 * 4 + 0];
            w.y = s_tile[i][c4 * 4 + 1];
            w.z = s_tile[i][c4 * 4 + 2];
            w.w = s_tile[i][c4 * 4 + 3];
            *(float4*)(g_featT + ((size_t)(b * NP + i0 + i) << 6) + c4 * 4) = w;
        }
    } else {
        int c = t >> 3, j = t & 7;
        #pragma unroll
        for (int rep = 0; rep < 2; ++rep) {
            int i4 = j + rep * 8;
            float4 v = *(const float4*)(w_out + (size_t)c * CH + i4 * 4);
            s_tile[i4 * 4 + 0][c] = v.x;
            s_tile[i4 * 4 + 1][c] = v.y;
            s_tile[i4 * 4 + 2][c] = v.z;
            s_tile[i4 * 4 + 3][c] = v.w;
        }
        __syncthreads();
        int i = t >> 3;
        #pragma unroll
        for (int rep = 0; rep < 2; ++rep) {
            int c4 = j + rep * 8;
            float4 w;
            w.x = s_tile[i][c4 * 4 + 0];
            w.y = s_tile[i][c4 * 4 + 1];
            w.z = s_tile[i][c4 * 4 + 2];
            w.w = s_tile[i][c4 * 4 + 3];
            *(float4*)(g_woutT + (size_t)i * CH + c4 * 4) = w;
        }
    }
}

#define INSERT(dd, pi, sl) {                                                   \
    if ((dd) < d2b || ((dd) == d2b && (pi) < i2)) {                            \
        if ((dd) < d1 || ((dd) == d1 && (pi) < i1)) {                          \
            d2b = d1; i2 = i1; s2 = s1;                                        \
            if ((dd) < d0 || ((dd) == d0 && (pi) < i0))                        \
                 { d1 = d0; i1 = i0; s1 = s0; d0 = (dd); i0 = (pi); s0 = (sl); } \
            else { d1 = (dd); i1 = (pi); s1 = (sl); }                          \
        } else { d2b = (dd); i2 = (pi); s2 = (sl); }                           \
    } }

// SMEM (floats): consts[352) | featR[48*68) | UNION{ cand+claim+map | fin[64*64] }
#define SM_W2A   0
#define SM_W2B   64
#define SM_W2C   128
#define SM_B2    192
#define SM_BOUT  256
#define SM_W1    320
#define SM_B1    336
#define SM_FEAT  352
#define SM_UNION (SM_FEAT + UMAX * FPAD)        // 352 + 3264 = 3616
#define SM_PX    SM_UNION
#define SM_PY    (SM_PX + CPAD)
#define SM_PSQ   (SM_PY + CPAD)
#define SM_IDX   (SM_PSQ + CPAD)
#define SM_CLAIM (SM_IDX + CPAD)
#define SM_MAP   (SM_CLAIM + CPAD)
#define SM_FIN   SM_UNION
#define UNION_FLOATS ((CH*PXB) > (6*CPAD) ? (CH*PXB) : (6*CPAD))
#define SMEM_FLOATS (SM_UNION + UNION_FLOATS)   // 3616 + 4096 = 7712
#define SMEM_BYTES  (SMEM_FLOATS * 4)           // 30848

__global__ __launch_bounds__(TPB, 7)
void k_main(const float* __restrict__ w1, const float* __restrict__ b1,
            const float* __restrict__ w2, const float* __restrict__ b2,
            const float* __restrict__ b_out,
            float* __restrict__ out)
{
    extern __shared__ float sm[];
    float* featR   = sm + SM_FEAT;
    float* candPx  = sm + SM_PX;
    float* candPy  = sm + SM_PY;
    float* candPsq = sm + SM_PSQ;
    int*   candIdx = (int*)(sm + SM_IDX);
    int*   claimA  = (int*)(sm + SM_CLAIM);
    int*   mapA    = (int*)(sm + SM_MAP);
    float* fin_s   = sm + SM_FIN;
    float* w2aF = sm + SM_W2A; float* w2bF = sm + SM_W2B; float* w2cF = sm + SM_W2C;
    float* b2F  = sm + SM_B2;  float* boutF = sm + SM_BOUT;
    float* w1s = sm + SM_W1;   float* b1s = sm + SM_B1;
    __shared__ int s_startA[3], s_cntA[3], s_offA[3], s_totalA;
    __shared__ int uniqIdx[UMAX];
    __shared__ int sh_ucnt;

    const int tid = threadIdx.x;
    const int b   = blockIdx.z;
    const int tx  = tid & 7, ty = tid >> 3;        // 8x8 pixel tile = 1x1 bin
    const int gxi = blockIdx.x * 8 + tx;
    const int gyi = blockIdx.y * 8 + ty;
    const float gx = (float)gxi, gy = (float)gyi;
    const float qsq = gx * gx + gy * gy;           // exact for integer coords

    // candidate ring: 3x3 bins
    const int tbx0 = blockIdx.x;
    const int tby0 = blockIdx.y;
    const int bxlo = max(tbx0 - 1, 0), bxhi = min(tbx0 + 1, NBX - 1);
    const int bylo = max(tby0 - 1, 0), byhi = min(tby0 + 1, NBY - 1);
    const int nrows = byhi - bylo + 1;

    if (tid < nrows) {
        int row = bylo + tid;
        int s = g_prefix[b * (NBINS + 1) + row * NBX + bxlo];
        int e = g_prefix[b * (NBINS + 1) + row * NBX + bxhi + 1];
        s_startA[tid] = s; s_cntA[tid] = e - s;
    }
    for (int i = tid; i < CAND_MAX; i += TPB) claimA[i] = 0;
    if (tid == 0) sh_ucnt = 0;
    if (tid < CH) {
        w2aF[tid] = w2[tid * 3 + 0];
        w2bF[tid] = w2[tid * 3 + 1];
        w2cF[tid] = w2[tid * 3 + 2];
        b2F[tid]  = b2[tid];
        boutF[tid] = b_out[tid];
    }
    if (tid < 9) w1s[tid] = w1[tid];
    if (tid < 3) b1s[tid] = b1[tid];
    __syncthreads();
    if (tid == 0) {
        int off = 0;
        for (int r = 0; r < nrows; ++r) { s_offA[r] = off; off += s_cntA[r]; }
        s_totalA = off;
    }
    __syncthreads();
    const int total = s_totalA;
    const bool ovf = total > CAND_MAX;
    if (!ovf) {
        for (int r = 0; r < nrows; ++r) {
            int c = s_cntA[r], st = s_startA[r], of = s_offA[r];
            for (int i = tid; i < c; i += TPB) {
                float4 p = g_binned[b * NP + st + i];
                candPx[of + i] = p.x; candPy[of + i] = p.y;
                candPsq[of + i] = p.z; candIdx[of + i] = __float_as_int(p.w);
            }
        }
        if (tid < 8) {
            candPx[total + tid] = 0.f; candPy[total + tid] = 0.f;
            candPsq[total + tid] = 1e30f; candIdx[total + tid] = 0x7ffffff0;
        }
    }
    __syncthreads();

    // ---- Phase 1: KNN, 4 candidates/iter; quad-min pre-guard ----
    float d0 = INFINITY, d1 = INFINITY, d2b = INFINITY;
    int   i0 = 0x7fffffff, i1 = 0x7fffffff, i2 = 0x7fffffff;
    int   s0 = 0, s1 = 0, s2 = 0;
    bool  fb = false;
    if (!ovf) {
        const float4* px4  = (const float4*)candPx;
        const float4* py4  = (const float4*)candPy;
        const float4* psq4 = (const float4*)candPsq;
        const ull gx2 = pk2(gx, gx), gy2 = pk2(gy, gy), qsq2 = pk2(qsq, qsq);
        int nq = (total + 3) >> 2;
        #pragma unroll 2
        for (int jq = 0; jq < nq; ++jq) {
            float4 PX = px4[jq], PY = py4[jq], PSQ = psq4[jq];
            ull crA = fma2_(pk2(PY.x, PY.y), gy2, mul2_(pk2(PX.x, PX.y), gx2));
            ull ddA = sub2_(add2_(qsq2, pk2(PSQ.x, PSQ.y)), add2_(crA, crA));
            ull crB = fma2_(pk2(PY.z, PY.w), gy2, mul2_(pk2(PX.z, PX.w), gx2));
            ull ddB = sub2_(add2_(qsq2, pk2(PSQ.z, PSQ.w)), add2_(crB, crB));
            float a0, a1, a2, a3;
            upk2(a0, a1, ddA); upk2(a2, a3, ddB);
            // quad-min guard: any insertable candidate satisfies dd <= d2b
            float mAll = fminf(fminf(a0, a1), fminf(a2, a3));
            if (mAll <= d2b) {
                int base = 4 * jq;
                if (a0 <= d2b) { int pi = candIdx[base + 0]; INSERT(a0, pi, base + 0); }
                if (a1 <= d2b) { int pi = candIdx[base + 1]; INSERT(a1, pi, base + 1); }
                if (a2 <= d2b) { int pi = candIdx[base + 2]; INSERT(a2, pi, base + 2); }
                if (a3 <= d2b) { int pi = candIdx[base + 3]; INSERT(a3, pi, base + 3); }
            }
        }
    }
    // completeness: any excluded point is >= dmin away
    float dl = (bxlo > 0)       ? (gx - (float)(bxlo * BSZ))       : 1e9f;
    float dr = (bxhi < NBX - 1) ? ((float)((bxhi + 1) * BSZ) - gx) : 1e9f;
    float dt = (bylo > 0)       ? (gy - (float)(bylo * BSZ))       : 1e9f;
    float db = (byhi < NBY - 1) ? ((float)((byhi + 1) * BSZ) - gy) : 1e9f;
    float dmin = fminf(fminf(dl, dr), fminf(dt, db));
    if (ovf || !(d2b + 0.25f <= dmin * dmin)) {    // rare exact fallback
        fb = true;
        d0 = d1 = d2b = INFINITY; i0 = i1 = i2 = 0x7fffffff;
        const float4* gp = g_binned + b * NP;
        #pragma unroll 4
        for (int j = 0; j < NP; ++j) {
            float4 p = gp[j];
            float cr = __fmaf_rn(p.y, gy, __fmul_rn(p.x, gx));
            float dd = __fsub_rn(__fadd_rn(qsq, p.z), __fadd_rn(cr, cr));
            if (dd <= d2b) { int pi = __float_as_int(p.w); INSERT(dd, pi, j); }
        }
    }

    // ---- Geometry -> h (registers) ----
    int nidx[3] = { i0, i1, i2 };
    int nsl[3]  = { s0, s1, s2 };
    ull hp0[3], hp1[3], hp2[3];
    #pragma unroll
    for (int k = 0; k < 3; ++k) {
        float pxx, pyy;
        if (!fb) { pxx = candPx[nsl[k]]; pyy = candPy[nsl[k]]; }
        else     { float4 p = g_binned[b * NP + nsl[k]]; pxx = p.x; pyy = p.y; }
        float dx = __fsub_rn(pxx, gx);
        float dy = __fsub_rn(pyy, gy);
        float nrm = __fsqrt_rn(__fadd_rn(__fmul_rn(dx, dx), __fmul_rn(dy, dy)));
        float h[3];
        #pragma unroll
        for (int j = 0; j < 3; ++j) {
            float t = __fmaf_rn(w1s[j*3+2], nrm,
                      __fmaf_rn(w1s[j*3+1], dy, __fmul_rn(w1s[j*3+0], dx)));
            t = t + b1s[j];
            h[j] = (t >= 0.f) ? t : 0.1f * t;
        }
        hp0[k] = pk2(h[0], h[0]); hp1[k] = pk2(h[1], h[1]); hp2[k] = pk2(h[2], h[2]);
    }

    // ---- Unique-neighbor dedup: claim, compact, coalesced row load ----
    if (!fb && !ovf) {
        #pragma unroll
        for (int k = 0; k < 3; ++k) {
            int s = nsl[k];
            if (atomicExch(&claimA[s], 1) == 0) {
                int u = atomicAdd(&sh_ucnt, 1);
                if (u < UMAX) { uniqIdx[u] = nidx[k]; mapA[s] = u; }
                else          { mapA[s] = -1; }
            }
        }
    }
    __syncthreads();
    int u0 = -1, u1 = -1, u2 = -1;
    if (!fb && !ovf) { u0 = mapA[nsl[0]]; u1 = mapA[nsl[1]]; u2 = mapA[nsl[2]]; }
    {
        int ucount = min(sh_ucnt, UMAX);
        for (int i = tid; i < ucount * 16; i += TPB) {
            int u = i >> 4, c4 = i & 15;
            float4 v = ((const float4*)(g_featT + ((size_t)(b * NP + uniqIdx[u]) << 6)))[c4];
            ((float4*)(featR + u * FPAD))[c4] = v;
        }
    }
    __syncthreads();   // featRows ready; cand/claim/map dead -> fin may overwrite

    // ---- Phase 2: score + gather -> fin_s[c][px] ----
    {
        const ull HALF2 = 0x3F0000003F000000ULL;
        const ull* w2a2 = (const ull*)w2aF;
        const ull* w2b2 = (const ull*)w2bF;
        const ull* w2c2 = (const ull*)w2cF;
        const ull* b2p2 = (const ull*)b2F;
        const ulonglong2* fr0 = (const ulonglong2*)(g_featT + ((size_t)(b * NP + nidx[0]) << 6));
        const ulonglong2* fr1 = (const ulonglong2*)(g_featT + ((size_t)(b * NP + nidx[1]) << 6));
        const ulonglong2* fr2 = (const ulonglong2*)(g_featT + ((size_t)(b * NP + nidx[2]) << 6));
        #pragma unroll 4
        for (int c8 = 0; c8 < 16; ++c8) {
            int c2 = 2 * c8;
            ull wa0 = w2a2[c2],   wb0 = w2b2[c2],   wc0 = w2c2[c2],   bb0 = b2p2[c2];
            ull wa1 = w2a2[c2+1], wb1 = w2b2[c2+1], wc1 = w2c2[c2+1], bb1 = b2p2[c2+1];
            ulonglong2 fA = (u0 >= 0) ? *(const ulonglong2*)(featR + u0 * FPAD + c8 * 4) : fr0[c8];
            ulonglong2 fB = (u1 >= 0) ? *(const ulonglong2*)(featR + u1 * FPAD + c8 * 4) : fr1[c8];
            ulonglong2 fC = (u2 >= 0) ? *(const ulonglong2*)(featR + u2 * FPAD + c8 * 4) : fr2[c8];
            ull uacc0 = 0ull, uacc1 = 0ull;
            #pragma unroll
            for (int k = 0; k < 3; ++k) {
                ulonglong2 f = (k == 0) ? fA : (k == 1) ? fB : fC;
                ull z0 = fma2_(wc0, hp2[k], fma2_(wb0, hp1[k], fma2_(wa0, hp0[k], bb0)));
                ull z1 = fma2_(wc1, hp2[k], fma2_(wb1, hp1[k], fma2_(wa1, hp0[k], bb1)));
                z0 = mul2_(z0, HALF2); z1 = mul2_(z1, HALF2);
                float za, zb, zc, zd;
                upk2(za, zb, z0); upk2(zc, zd, z1);
                float sa = __fmaf_rn(0.5f, tanh_ap(za), 0.5f);
                float sb = __fmaf_rn(0.5f, tanh_ap(zb), 0.5f);
                float sc = __fmaf_rn(0.5f, tanh_ap(zc), 0.5f);
                float sd = __fmaf_rn(0.5f, tanh_ap(zd), 0.5f);
                uacc0 = fma2_(pk2(sa, sb), f.x, uacc0);
                uacc1 = fma2_(pk2(sc, sd), f.y, uacc1);
            }
            float v0, v1, v2, v3;
            upk2(v0, v1, uacc0); upk2(v2, v3, uacc1);
            int cb = 4 * c8;
            fin_s[(cb + 0) * PXB + tid] = v0;
            fin_s[(cb + 1) * PXB + tid] = v1;
            fin_s[(cb + 2) * PXB + tid] = v2;
            fin_s[(cb + 3) * PXB + tid] = v3;
        }
    }
    __syncthreads();

    // ---- Phase 3: block GEMM 64px x 64co, thread = 8px x 8co ----
    const int p0 = 8 * (tid & 7);
    const int c0 = 8 * (tid >> 3);
    ull acc[8][4];
    #pragma unroll
    for (int p = 0; p < 8; ++p)
        #pragma unroll
        for (int j = 0; j < 4; ++j) acc[p][j] = 0ull;

    #pragma unroll 4
    for (int c = 0; c < CH; ++c) {
        const float4* frp = (const float4*)(fin_s + c * PXB + p0);
        float4 fA = frp[0], fB = frp[1];
        const ulonglong2* wg = (const ulonglong2*)(g_woutT + c * CH + c0);
        ulonglong2 w01 = wg[0], w23 = wg[1];
        ull fp;
        fp = pk2(fA.x, fA.x);
        acc[0][0]=fma2_(w01.x,fp,acc[0][0]); acc[0][1]=fma2_(w01.y,fp,acc[0][1]);
        acc[0][2]=fma2_(w23.x,fp,acc[0][2]); acc[0][3]=fma2_(w23.y,fp,acc[0][3]);
        fp = pk2(fA.y, fA.y);
        acc[1][0]=fma2_(w01.x,fp,acc[1][0]); acc[1][1]=fma2_(w01.y,fp,acc[1][1]);
        acc[1][2]=fma2_(w23.x,fp,acc[1][2]); acc[1][3]=fma2_(w23.y,fp,acc[1][3]);
        fp = pk2(fA.z, fA.z);
        acc[2][0]=fma2_(w01.x,fp,acc[2][0]); acc[2][1]=fma2_(w01.y,fp,acc[2][1]);
        acc[2][2]=fma2_(w23.x,fp,acc[2][2]); acc[2][3]=fma2_(w23.y,fp,acc[2][3]);
        fp = pk2(fA.w, fA.w);
        acc[3][0]=fma2_(w01.x,fp,acc[3][0]); acc[3][1]=fma2_(w01.y,fp,acc[3][1]);
        acc[3][2]=fma2_(w23.x,fp,acc[3][2]); acc[3][3]=fma2_(w23.y,fp,acc[3][3]);
        fp = pk2(fB.x, fB.x);
        acc[4][0]=fma2_(w01.x,fp,acc[4][0]); acc[4][1]=fma2_(w01.y,fp,acc[4][1]);
        acc[4][2]=fma2_(w23.x,fp,acc[4][2]); acc[4][3]=fma2_(w23.y,fp,acc[4][3]);
        fp = pk2(fB.y, fB.y);
        acc[5][0]=fma2_(w01.x,fp,acc[5][0]); acc[5][1]=fma2_(w01.y,fp,acc[5][1]);
        acc[5][2]=fma2_(w23.x,fp,acc[5][2]); acc[5][3]=fma2_(w23.y,fp,acc[5][3]);
        fp = pk2(fB.z, fB.z);
        acc[6][0]=fma2_(w01.x,fp,acc[6][0]); acc[6][1]=fma2_(w01.y,fp,acc[6][1]);
        acc[6][2]=fma2_(w23.x,fp,acc[6][2]); acc[6][3]=fma2_(w23.y,fp,acc[6][3]);
        fp = pk2(fB.w, fB.w);
        acc[7][0]=fma2_(w01.x,fp,acc[7][0]); acc[7][1]=fma2_(w01.y,fp,acc[7][1]);
        acc[7][2]=fma2_(w23.x,fp,acc[7][2]); acc[7][3]=fma2_(w23.y,fp,acc[7][3]);
    }

    // epilogue: pixels p0..p0+7 = image row (tid&7), cols 0..7 of the tile
    {
        const int row = tid & 7;
        const int q0  = (blockIdx.y * 8 + row) * IMW + blockIdx.x * 8;
        float* outb = out + ((size_t)b * CH) * QPB + q0;
        #pragma unroll
        for (int j = 0; j < 4; ++j) {
            float lo[8], hi[8];
            #pragma unroll
            for (int p = 0; p < 8; ++p) upk2(lo[p], hi[p], acc[p][j]);
            int coA = c0 + 2 * j, coB = coA + 1;
            float bA = boutF[coA], bB = boutF[coB];
            #pragma unroll
            for (int p = 0; p < 8; ++p) {
                lo[p] += bA; lo[p] = (lo[p] >= 0.f) ? lo[p] : 0.1f * lo[p];
                hi[p] += bB; hi[p] = (hi[p] >= 0.f) ? hi[p] : 0.1f * hi[p];
            }
            float* oA = outb + (size_t)coA * QPB;
            float* oB = outb + (size_t)coB * QPB;
            *(float4*)(oA)     = make_float4(lo[0], lo[1], lo[2], lo[3]);
            *(float4*)(oA + 4) = make_float4(lo[4], lo[5], lo[6], lo[7]);
            *(float4*)(oB)     = make_float4(hi[0], hi[1], hi[2], hi[3]);
            *(float4*)(oB + 4) = make_float4(hi[4], hi[5], hi[6], hi[7]);
        }
    }
}

extern "C" void kernel_launch(void* const* d_in, const int* in_sizes, int n_in,
                              void* d_out, int out_size) {
    const float* uv    = (const float*)d_in[0];
    const float* feat  = (const float*)d_in[1];
    const float* w1    = (const float*)d_in[4];
    const float* b1    = (const float*)d_in[5];
    const float* w2    = (const float*)d_in[6];
    const float* b2    = (const float*)d_in[7];
    const float* w_out = (const float*)d_in[8];
    const float* b_out = (const float*)d_in[9];
    float* out = (float*)d_out;

    k_prep<<<BS + BS * 64 + 1, 512>>>(uv, feat, w_out);

    cudaFuncSetAttribute(k_main, cudaFuncAttributeMaxDynamicSharedMemorySize, SMEM_BYTES);
    dim3 grid(IMW / 8, IMH / 8, BS);
    k_main<<<grid, TPB, SMEM_BYTES>>>(w1, b1, w2, b2, b_out, out);
}